// round 5
// baseline (speedup 1.0000x reference)
#include <cuda_runtime.h>
#include <cstdint>

#define IC    1024   // input capsules
#define CDIM  256    // input dim
#define NC    16     // num output capsules
#define DD    32     // capsule dim
#define CH    64     // i-chunk rows staged in smem
#define NCHUNK (IC / CH)
#define THREADS 1024
#define EPS 1e-7f

// ---- smem layout (float offsets) ----
#define OFF_U     0                       // 2 * 64*256 = 32768 floats (double buffer, xor-swizzled)
#define OFF_VPART 0                       // aliases U ring: only live after chunk loop (16384 fl)
#define OFF_W     32768                   // 16*256 = 4096
#define OFF_BLOG  36864                   // 16 kg * 16 n * 65 = 16640 (also pass-0 scratch)
#define OFF_CS    53504                   // 64 rows * 16 n = 1024 (transposed [row][n])
#define OFF_OUT   54528                   // 16*32 = 512
#define OFF_USUM  55040                   // 256
#define SMEM_FLOATS 55296
#define SMEM_BYTES (SMEM_FLOATS * 4)      // 221184 B

// ---- packed f32x2 helpers (sm_100+) ----
__device__ __forceinline__ unsigned long long ffma2(unsigned long long a, unsigned long long b,
                                                    unsigned long long c) {
    unsigned long long d;
    asm("fma.rn.f32x2 %0, %1, %2, %3;" : "=l"(d) : "l"(a), "l"(b), "l"(c));
    return d;
}
__device__ __forceinline__ unsigned long long pk2(float v) {
    unsigned long long d; asm("mov.b64 %0, {%1, %1};" : "=l"(d) : "f"(v)); return d;
}
__device__ __forceinline__ float2 upk(unsigned long long d) {
    float2 r; asm("mov.b64 {%0, %1}, %2;" : "=f"(r.x), "=f"(r.y) : "l"(d)); return r;
}

__device__ __forceinline__ void prefetch_chunk(float* sm, const float* u, int chunk, int buf, int t) {
    const float* src = u + (size_t)chunk * CH * CDIM;
#pragma unroll
    for (int k = 0; k < 4; k++) {
        int idx = t + k * THREADS;        // 0..4095 (64 rows * 64 float4)
        int row = idx >> 6;
        int c4  = idx & 63;
        float* dstp = &sm[OFF_U + buf * (CH * CDIM) + row * CDIM + ((c4 ^ (row & 15)) << 2)];
        unsigned dst = (unsigned)__cvta_generic_to_shared(dstp);
        const float* g = src + row * CDIM + c4 * 4;
        asm volatile("cp.async.cg.shared.global [%0], [%1], 16;" :: "r"(dst), "l"(g));
    }
    asm volatile("cp.async.commit_group;");
}

// Per-warp (warp == capsule n, wid<16): s[n] = scale * (vsrc . W_n), squash -> out.
// If gout != nullptr: write final output and return. Else write out_s and w_s[n][c] = W_n @ out.
__device__ __forceinline__ void boundary(float* sm, const float* vsrc_base, int per_n_stride,
                                         float scale, const float* __restrict__ W,
                                         bool write_w, float* gout, int wid, int lane) {
    const float* vsrc = vsrc_base + wid * per_n_stride;
    const float* Wp = W + wid * DD + lane;       // W[c*512 + n*32 + d]
    float s = 0.f;
#pragma unroll 8
    for (int c = 0; c < CDIM; c++) s += vsrc[c] * Wp[c * (NC * DD)];
    s *= scale;
    float ss = s * s;
#pragma unroll
    for (int o = 16; o > 0; o >>= 1) ss += __shfl_xor_sync(0xffffffffu, ss, o);
    float ov = s * rsqrtf(ss + EPS);
    if (gout) { gout[wid * DD + lane] = ov; return; }
    sm[OFF_OUT + wid * DD + lane] = ov;
    __syncwarp();
    if (write_w) {
#pragma unroll
        for (int k = 0; k < 8; k++) {
            int c = lane + 32 * k;
            const float* Wc = W + c * (NC * DD) + wid * DD;
            float a = 0.f;
#pragma unroll
            for (int dd = 0; dd < DD; dd += 4) {
                float4 w4 = *(const float4*)(Wc + dd);
                a += w4.x * sm[OFF_OUT + wid * DD + dd + 0];
                a += w4.y * sm[OFF_OUT + wid * DD + dd + 1];
                a += w4.z * sm[OFF_OUT + wid * DD + dd + 2];
                a += w4.w * sm[OFF_OUT + wid * DD + dd + 3];
            }
            sm[OFF_W + wid * CDIM + c] = a;
        }
    }
}

__global__ __launch_bounds__(THREADS, 1)
void caps_route_kernel(const float* __restrict__ u_vecs, const float* __restrict__ W,
                       float* __restrict__ gout) {
    extern __shared__ float sm[];
    const int t = threadIdx.x, wid = t >> 5, lane = t & 31;
    const int b = blockIdx.x;
    const float* u = u_vecs + (size_t)b * IC * CDIM;

    // step-A roles: warp = (kg in 16, row-half in 2); lane = row within half
    const int a_kg  = wid & 15;
    const int a_row = ((wid >> 4) << 5) + lane;       // 0..63

    // step-C roles: warp = (n-quad, ch-half, row-group of 16); lane = ch-quad within half
    const int c_n4   = wid & 3;             // n in n4*4..+4
    const int c_chh  = (wid >> 2) & 1;      // channel half
    const int c_rgrp = wid >> 3;            // row group of 16 (0..3)
    const int c_Q    = c_chh * 32 + lane;   // channel quad 0..63

    // ---------- pass 0: usum[c] = sum_i u[i][c]; out0 = squash(usum/16 @ W_n) ----------
    {
        int c4 = t & 63, rg = t >> 6;     // 16 row groups x 64 quads
        const float* up = u + (size_t)rg * CDIM + c4 * 4;
        float4 a = make_float4(0.f, 0.f, 0.f, 0.f);
#pragma unroll 8
        for (int i = 0; i < IC / 16; i++) {
            float4 v = *(const float4*)(up + (size_t)i * 16 * CDIM);
            a.x += v.x; a.y += v.y; a.z += v.z; a.w += v.w;
        }
        *(float4*)&sm[OFF_BLOG + rg * CDIM + c4 * 4] = a;
    }
    __syncthreads();
    if (t < 256) {
        float a = 0.f;
#pragma unroll
        for (int rg = 0; rg < 16; rg++) a += sm[OFF_BLOG + rg * CDIM + t];
        sm[OFF_USUM + t] = a;
    }
    __syncthreads();
    if (wid < 16) boundary(sm, &sm[OFF_USUM], 0, 1.f / 16.f, W, true, nullptr, wid, lane);
    __syncthreads();

    // ---------- 2 fused routing passes ----------
    for (int pass = 0; pass < 2; ++pass) {
        unsigned long long vac2[4][2];     // 4 capsules x 2 channel-pairs (4 channels)
#pragma unroll
        for (int m = 0; m < 4; m++) { vac2[m][0] = 0ull; vac2[m][1] = 0ull; }

        prefetch_chunk(sm, u, 0, 0, t);

        for (int chunk = 0; chunk < NCHUNK; ++chunk) {
            asm volatile("cp.async.wait_group 0;" ::: "memory");
            __syncthreads();
            if (chunk + 1 < NCHUNK) prefetch_chunk(sm, u, chunk + 1, (chunk + 1) & 1, t);
            const float* ub = &sm[OFF_U + (chunk & 1) * (CH * CDIM)];

            // --- step A: blog[n][row] partials, k-split 16 x 16 ch, 1 row/lane ---
            {
                const int s = a_row & 15;
                const float* rb = ub + a_row * CDIM;
                ulonglong2 uq[4];
#pragma unroll
                for (int j = 0; j < 4; j++)
                    uq[j] = *(const ulonglong2*)(rb + (((a_kg * 4 + j) ^ s) << 2));
#pragma unroll
                for (int n = 0; n < NC; n++) {
                    const float* wb = &sm[OFF_W + n * CDIM + a_kg * 16];
                    unsigned long long a0 = 0ull;
#pragma unroll
                    for (int j = 0; j < 4; j++) {
                        ulonglong2 w2 = *(const ulonglong2*)(wb + 4 * j);
                        a0 = ffma2(uq[j].x, w2.x, a0);
                        a0 = ffma2(uq[j].y, w2.y, a0);
                    }
                    float2 f0 = upk(a0);
                    sm[OFF_BLOG + a_kg * (NC * 65) + n * 65 + a_row] = f0.x + f0.y;
                }
            }
            __syncthreads();

            // --- softmax over n (per row): one (row, n) per thread ---
            {
                const int n = t & 15, ii = t >> 4;   // ii = row 0..63
                float bl = 0.f;
#pragma unroll
                for (int kg = 0; kg < 16; kg++)
                    bl += sm[OFF_BLOG + kg * (NC * 65) + n * 65 + ii];
                float m = bl;
#pragma unroll
                for (int o = 8; o > 0; o >>= 1) m = fmaxf(m, __shfl_xor_sync(0xffffffffu, m, o, 16));
                float e = __expf(bl - m);
                float ssum = e;
#pragma unroll
                for (int o = 8; o > 0; o >>= 1) ssum += __shfl_xor_sync(0xffffffffu, ssum, o, 16);
                sm[OFF_CS + ii * NC + n] = e / ssum;   // transposed [row][n]
            }
            __syncthreads();

            // --- step C: v[n][c] += c[n][row] * u[row][c]; 4 n x 4 ch per thread, 16 rows ---
            {
                const float* csb = &sm[OFF_CS + c_n4 * 4];
#pragma unroll 4
                for (int r16 = 0; r16 < 16; r16++) {
                    int row = c_rgrp * 16 + r16;
                    ulonglong2 uu = *(const ulonglong2*)(ub + row * CDIM + ((c_Q ^ (row & 15)) << 2));
                    float4 ca = *(const float4*)(csb + row * NC);   // c[n4*4 .. +4][row]
                    unsigned long long c0 = pk2(ca.x), c1 = pk2(ca.y), c2 = pk2(ca.z), c3 = pk2(ca.w);
                    vac2[0][0] = ffma2(uu.x, c0, vac2[0][0]);
                    vac2[0][1] = ffma2(uu.y, c0, vac2[0][1]);
                    vac2[1][0] = ffma2(uu.x, c1, vac2[1][0]);
                    vac2[1][1] = ffma2(uu.y, c1, vac2[1][1]);
                    vac2[2][0] = ffma2(uu.x, c2, vac2[2][0]);
                    vac2[2][1] = ffma2(uu.y, c2, vac2[2][1]);
                    vac2[3][0] = ffma2(uu.x, c3, vac2[3][0]);
                    vac2[3][1] = ffma2(uu.y, c3, vac2[3][1]);
                }
            }
        }
        __syncthreads();   // U ring dead; VPART (alias) becomes live

        // dump register v partials (4 rgrp copies), reduce
        {
#pragma unroll
            for (int m = 0; m < 4; m++) {
                int n = c_n4 * 4 + m;
                float* base = &sm[OFF_VPART + c_rgrp * (NC * CDIM) + n * CDIM + c_Q * 4];
                *(unsigned long long*)(base + 0) = vac2[m][0];
                *(unsigned long long*)(base + 2) = vac2[m][1];
            }
        }
        __syncthreads();
        {
            int q = t;    // NC*CDIM/4 = 1024 quads == THREADS
            float4 a = *(float4*)&sm[OFF_VPART + 4 * q];
            float4 b1 = *(float4*)&sm[OFF_VPART + 1 * NC * CDIM + 4 * q];
            float4 b2 = *(float4*)&sm[OFF_VPART + 2 * NC * CDIM + 4 * q];
            float4 b3 = *(float4*)&sm[OFF_VPART + 3 * NC * CDIM + 4 * q];
            a.x += b1.x + b2.x + b3.x;
            a.y += b1.y + b2.y + b3.y;
            a.z += b1.z + b2.z + b3.z;
            a.w += b1.w + b2.w + b3.w;
            *(float4*)&sm[OFF_VPART + 4 * q] = a;
        }
        __syncthreads();

        bool last = (pass == 1);
        if (wid < 16)
            boundary(sm, &sm[OFF_VPART], CDIM, 1.f, W, !last,
                     last ? (gout + (size_t)b * NC * DD) : nullptr, wid, lane);
        __syncthreads();   // protects next pass's prefetch into aliased U ring
    }
}

extern "C" void kernel_launch(void* const* d_in, const int* in_sizes, int n_in,
                              void* d_out, int out_size) {
    const float* u_vecs = (const float*)d_in[0];   // (128, 1024, 256) fp32
    const float* W      = (const float*)d_in[1];   // (256, 512) fp32
    float* out          = (float*)d_out;           // (128, 16, 32) fp32

    cudaFuncSetAttribute(caps_route_kernel, cudaFuncAttributeMaxDynamicSharedMemorySize, SMEM_BYTES);
    caps_route_kernel<<<128, THREADS, SMEM_BYTES>>>(u_vecs, W, out);
}

// round 6
// speedup vs baseline: 1.0656x; 1.0656x over previous
#include <cuda_runtime.h>
#include <cstdint>

#define IC    1024   // input capsules
#define CDIM  256    // input dim
#define NC    16     // num output capsules
#define DD    32     // capsule dim
#define CH    32     // rows per group-chunk
#define NCHUNK (IC / CH)      // 32
#define THREADS 1024
#define GSIZE 512
#define EPS 1e-7f

// ---- smem layout (float offsets) ----
#define OFF_U     0                       // 4 stages * 32*256 = 32768 floats (xor-swizzled)
#define OFF_VPART 0                       // aliases U ring (4*16*256 = 16384 fl, post-loop only)
#define OFF_W     32768                   // 16*256 = 4096
#define OFF_BLOG  36864                   // per group: 16kg*16n*33 = 8448; x2 = 16896
#define OFF_CS    53760                   // per group: 32*16 = 512; x2 = 1024
#define OFF_OUT   54784                   // 16*32 = 512
#define OFF_USUM  55296                   // 256
#define SMEM_FLOATS 55552
#define SMEM_BYTES (SMEM_FLOATS * 4)      // 222208 B

#define GBAR(g) asm volatile("bar.sync %0, %1;" :: "r"((g) + 1), "r"(GSIZE) : "memory")

// ---- packed f32x2 helpers (sm_100+) ----
__device__ __forceinline__ unsigned long long ffma2(unsigned long long a, unsigned long long b,
                                                    unsigned long long c) {
    unsigned long long d;
    asm("fma.rn.f32x2 %0, %1, %2, %3;" : "=l"(d) : "l"(a), "l"(b), "l"(c));
    return d;
}
__device__ __forceinline__ unsigned long long pk2(float v) {
    unsigned long long d; asm("mov.b64 %0, {%1, %1};" : "=l"(d) : "f"(v)); return d;
}
__device__ __forceinline__ float2 upk(unsigned long long d) {
    float2 r; asm("mov.b64 {%0, %1}, %2;" : "=f"(r.x), "=f"(r.y) : "l"(d)); return r;
}

// 512-thread prefetch of one 32x256 chunk into ring stage
__device__ __forceinline__ void prefetch_chunk(float* sm, const float* u, int chunk, int gt) {
    const float* src = u + (size_t)chunk * CH * CDIM;
    int stage = chunk & 3;
#pragma unroll
    for (int k = 0; k < 4; k++) {
        int idx = gt + k * GSIZE;         // 0..2047 (32 rows * 64 float4)
        int row = idx >> 6;
        int c4  = idx & 63;
        float* dstp = &sm[OFF_U + stage * (CH * CDIM) + row * CDIM + ((c4 ^ (row & 15)) << 2)];
        unsigned dst = (unsigned)__cvta_generic_to_shared(dstp);
        const float* g = src + row * CDIM + c4 * 4;
        asm volatile("cp.async.cg.shared.global [%0], [%1], 16;" :: "r"(dst), "l"(g));
    }
    asm volatile("cp.async.commit_group;");
}

// Per-warp (warp == capsule n, wid<16): s[n] = scale * (vsrc . W_n), squash -> out.
// If gout != nullptr: write final output and return. Else write out_s and w_s[n][c] = W_n @ out.
__device__ __forceinline__ void boundary(float* sm, const float* vsrc_base, int per_n_stride,
                                         float scale, const float* __restrict__ W,
                                         bool write_w, float* gout, int wid, int lane) {
    const float* vsrc = vsrc_base + wid * per_n_stride;
    const float* Wp = W + wid * DD + lane;       // W[c*512 + n*32 + d]
    float s = 0.f;
#pragma unroll 8
    for (int c = 0; c < CDIM; c++) s += vsrc[c] * Wp[c * (NC * DD)];
    s *= scale;
    float ss = s * s;
#pragma unroll
    for (int o = 16; o > 0; o >>= 1) ss += __shfl_xor_sync(0xffffffffu, ss, o);
    float ov = s * rsqrtf(ss + EPS);
    if (gout) { gout[wid * DD + lane] = ov; return; }
    sm[OFF_OUT + wid * DD + lane] = ov;
    __syncwarp();
    if (write_w) {
#pragma unroll
        for (int k = 0; k < 8; k++) {
            int c = lane + 32 * k;
            const float* Wc = W + c * (NC * DD) + wid * DD;
            float a = 0.f;
#pragma unroll
            for (int dd = 0; dd < DD; dd += 4) {
                float4 w4 = *(const float4*)(Wc + dd);
                a += w4.x * sm[OFF_OUT + wid * DD + dd + 0];
                a += w4.y * sm[OFF_OUT + wid * DD + dd + 1];
                a += w4.z * sm[OFF_OUT + wid * DD + dd + 2];
                a += w4.w * sm[OFF_OUT + wid * DD + dd + 3];
            }
            sm[OFF_W + wid * CDIM + c] = a;
        }
    }
}

__global__ __launch_bounds__(THREADS, 1)
void caps_route_kernel(const float* __restrict__ u_vecs, const float* __restrict__ W,
                       float* __restrict__ gout) {
    extern __shared__ float sm[];
    const int t = threadIdx.x, wid = t >> 5, lane = t & 31;
    const int g = wid >> 4;                // ping-pong group 0/1
    const int gt = t & (GSIZE - 1);        // thread id within group
    const int gwid = gt >> 5;              // warp id within group (0..15)
    const int b = blockIdx.x;
    const float* u = u_vecs + (size_t)b * IC * CDIM;

    float* blogg = &sm[OFF_BLOG + g * 8448];
    float* csg   = &sm[OFF_CS + g * 512];

    // step-C roles (within group): warp = (n4, chh, rgrp); lane = ch-quad within half
    const int c_n4   = gwid & 3;            // n in n4*4..+4
    const int c_chh  = (gwid >> 2) & 1;     // channel half
    const int c_rgrp = (gwid >> 3) & 1;     // row group of 16
    const int c_Q    = c_chh * 32 + lane;   // channel quad 0..63

    // ---------- pass 0: usum[c] = sum_i u[i][c]; out0 = squash(usum/16 @ W_n) ----------
    {
        int c4 = t & 63, rg = t >> 6;     // 16 row groups x 64 quads
        const float* up = u + (size_t)rg * CDIM + c4 * 4;
        float4 a = make_float4(0.f, 0.f, 0.f, 0.f);
#pragma unroll 8
        for (int i = 0; i < IC / 16; i++) {
            float4 v = *(const float4*)(up + (size_t)i * 16 * CDIM);
            a.x += v.x; a.y += v.y; a.z += v.z; a.w += v.w;
        }
        *(float4*)&sm[OFF_BLOG + rg * CDIM + c4 * 4] = a;
    }
    __syncthreads();
    if (t < 256) {
        float a = 0.f;
#pragma unroll
        for (int rg = 0; rg < 16; rg++) a += sm[OFF_BLOG + rg * CDIM + t];
        sm[OFF_USUM + t] = a;
    }
    __syncthreads();
    if (wid < 16) boundary(sm, &sm[OFF_USUM], 0, 1.f / 16.f, W, true, nullptr, wid, lane);
    __syncthreads();

    // ---------- 2 fused routing passes, ping-pong groups over chunk parity ----------
    for (int pass = 0; pass < 2; ++pass) {
        unsigned long long vac2[4][2];     // 4 capsules x 2 channel-pairs (4 channels)
#pragma unroll
        for (int m = 0; m < 4; m++) { vac2[m][0] = 0ull; vac2[m][1] = 0ull; }

        prefetch_chunk(sm, u, g, gt);
        prefetch_chunk(sm, u, g + 2, gt);

        for (int c = g; c < NCHUNK; c += 2) {
            if (c + 2 < NCHUNK) asm volatile("cp.async.wait_group 1;" ::: "memory");
            else                asm volatile("cp.async.wait_group 0;" ::: "memory");
            GBAR(g);
            const float* ub = &sm[OFF_U + (c & 3) * (CH * CDIM)];

            // --- step A: blog[n][row] partials, warp = kg (16 ch), lane = row ---
            {
                const int kg = gwid, s = lane & 15;
                const float* rb = ub + lane * CDIM;
                ulonglong2 uq[4];
#pragma unroll
                for (int j = 0; j < 4; j++)
                    uq[j] = *(const ulonglong2*)(rb + (((kg * 4 + j) ^ s) << 2));
#pragma unroll
                for (int n = 0; n < NC; n++) {
                    const float* wb = &sm[OFF_W + n * CDIM + kg * 16];
                    unsigned long long a0 = 0ull;
#pragma unroll
                    for (int j = 0; j < 4; j++) {
                        ulonglong2 w2 = *(const ulonglong2*)(wb + 4 * j);
                        a0 = ffma2(uq[j].x, w2.x, a0);
                        a0 = ffma2(uq[j].y, w2.y, a0);
                    }
                    float2 f0 = upk(a0);
                    blogg[kg * (NC * 33) + n * 33 + lane] = f0.x + f0.y;
                }
            }
            GBAR(g);

            // --- softmax over n: one (row, n) per thread (512 = 32 rows x 16 n) ---
            {
                const int n = gt & 15, ii = gt >> 4;
                float bl = 0.f;
#pragma unroll
                for (int kg = 0; kg < 16; kg++)
                    bl += blogg[kg * (NC * 33) + n * 33 + ii];
                float m = bl;
#pragma unroll
                for (int o = 8; o > 0; o >>= 1) m = fmaxf(m, __shfl_xor_sync(0xffffffffu, m, o, 16));
                float e = __expf(bl - m);
                float ssum = e;
#pragma unroll
                for (int o = 8; o > 0; o >>= 1) ssum += __shfl_xor_sync(0xffffffffu, ssum, o, 16);
                csg[ii * NC + n] = e / ssum;   // transposed [row][n]
            }
            GBAR(g);

            // --- step C: v[n][ch] += c[n][row] * u[row][ch]; 4 n x 4 ch, 16 rows ---
            {
                const float* csb = csg + c_n4 * 4;
#pragma unroll 4
                for (int r16 = 0; r16 < 16; r16++) {
                    int row = c_rgrp * 16 + r16;
                    ulonglong2 uu = *(const ulonglong2*)(ub + row * CDIM + ((c_Q ^ (row & 15)) << 2));
                    float4 ca = *(const float4*)(csb + row * NC);
                    unsigned long long c0 = pk2(ca.x), c1 = pk2(ca.y), c2 = pk2(ca.z), c3 = pk2(ca.w);
                    vac2[0][0] = ffma2(uu.x, c0, vac2[0][0]);
                    vac2[0][1] = ffma2(uu.y, c0, vac2[0][1]);
                    vac2[1][0] = ffma2(uu.x, c1, vac2[1][0]);
                    vac2[1][1] = ffma2(uu.y, c1, vac2[1][1]);
                    vac2[2][0] = ffma2(uu.x, c2, vac2[2][0]);
                    vac2[2][1] = ffma2(uu.y, c2, vac2[2][1]);
                    vac2[3][0] = ffma2(uu.x, c3, vac2[3][0]);
                    vac2[3][1] = ffma2(uu.y, c3, vac2[3][1]);
                }
            }
            GBAR(g);   // group done reading stage (c&3); safe to refill it

            if (c + 4 < NCHUNK) prefetch_chunk(sm, u, c + 4, gt);
        }
        __syncthreads();   // both groups done; U ring dead; VPART (alias) live

        // dump register v partials (copies: g*2 + rgrp), reduce 4 copies
        {
#pragma unroll
            for (int m = 0; m < 4; m++) {
                int n = c_n4 * 4 + m;
                float* base = &sm[OFF_VPART + (g * 2 + c_rgrp) * (NC * CDIM) + n * CDIM + c_Q * 4];
                *(unsigned long long*)(base + 0) = vac2[m][0];
                *(unsigned long long*)(base + 2) = vac2[m][1];
            }
        }
        __syncthreads();
        {
            int q = t;    // NC*CDIM/4 = 1024 quads == THREADS
            float4 a = *(float4*)&sm[OFF_VPART + 4 * q];
            float4 b1 = *(float4*)&sm[OFF_VPART + 1 * NC * CDIM + 4 * q];
            float4 b2 = *(float4*)&sm[OFF_VPART + 2 * NC * CDIM + 4 * q];
            float4 b3 = *(float4*)&sm[OFF_VPART + 3 * NC * CDIM + 4 * q];
            a.x += b1.x + b2.x + b3.x;
            a.y += b1.y + b2.y + b3.y;
            a.z += b1.z + b2.z + b3.z;
            a.w += b1.w + b2.w + b3.w;
            *(float4*)&sm[OFF_VPART + 4 * q] = a;
        }
        __syncthreads();

        bool last = (pass == 1);
        if (wid < 16)
            boundary(sm, &sm[OFF_VPART], CDIM, 1.f, W, !last,
                     last ? (gout + (size_t)b * NC * DD) : nullptr, wid, lane);
        __syncthreads();   // protects next pass's prefetch into aliased U ring
    }
}

extern "C" void kernel_launch(void* const* d_in, const int* in_sizes, int n_in,
                              void* d_out, int out_size) {
    const float* u_vecs = (const float*)d_in[0];   // (128, 1024, 256) fp32
    const float* W      = (const float*)d_in[1];   // (256, 512) fp32
    float* out          = (float*)d_out;           // (128, 16, 32) fp32

    cudaFuncSetAttribute(caps_route_kernel, cudaFuncAttributeMaxDynamicSharedMemorySize, SMEM_BYTES);
    caps_route_kernel<<<128, THREADS, SMEM_BYTES>>>(u_vecs, W, out);
}

// round 7
// speedup vs baseline: 1.0843x; 1.0176x over previous
#include <cuda_runtime.h>
#include <cstdint>

#define IC    1024   // input capsules
#define CDIM  256    // input dim
#define NC    16     // num output capsules
#define DD    32     // capsule dim
#define CH    64     // rows per group-chunk
#define NCHUNK (IC / CH)      // 16
#define THREADS 1024
#define GSIZE 512
#define EPS 1e-7f

// ---- smem layout (float offsets) ----
#define OFF_U     0                       // 2 bufs * 64*256 = 32768 floats (xor-swizzled)
#define OFF_VPART 0                       // aliases U (4 copies * 4096 = 16384, post-loop only)
#define OFF_W     32768                   // 16*256 = 4096
#define OFF_BLOG  36864                   // per group: 8 kg * 64 rows * 17 = 8704; x2 = 17408
#define OFF_CS    54272                   // per group: 64*16 = 1024; x2 = 2048
#define OFF_OUT   56320                   // 16*32 = 512
#define OFF_USUM  56832                   // 256
#define SMEM_FLOATS 57088
#define SMEM_BYTES (SMEM_FLOATS * 4)      // 228352 B  (< 232448 max)

#define GBAR(g) asm volatile("bar.sync %0, %1;" :: "r"((g) + 1), "r"(GSIZE) : "memory")

// ---- packed f32x2 helpers (sm_100+) ----
__device__ __forceinline__ unsigned long long ffma2(unsigned long long a, unsigned long long b,
                                                    unsigned long long c) {
    unsigned long long d;
    asm("fma.rn.f32x2 %0, %1, %2, %3;" : "=l"(d) : "l"(a), "l"(b), "l"(c));
    return d;
}
__device__ __forceinline__ unsigned long long pk2(float v) {
    unsigned long long d; asm("mov.b64 %0, {%1, %1};" : "=l"(d) : "f"(v)); return d;
}
__device__ __forceinline__ float2 upk(unsigned long long d) {
    float2 r; asm("mov.b64 {%0, %1}, %2;" : "=f"(r.x), "=f"(r.y) : "l"(d)); return r;
}

// 512-thread prefetch of one 64x256 chunk into group buffer
__device__ __forceinline__ void prefetch_chunk(float* sm, const float* u, int chunk, int buf, int gt) {
    const float* src = u + (size_t)chunk * CH * CDIM;
#pragma unroll
    for (int k = 0; k < 8; k++) {
        int idx = gt + k * GSIZE;         // 0..4095 (64 rows * 64 float4)
        int row = idx >> 6;
        int c4  = idx & 63;
        float* dstp = &sm[OFF_U + buf * (CH * CDIM) + row * CDIM + ((c4 ^ (row & 15)) << 2)];
        unsigned dst = (unsigned)__cvta_generic_to_shared(dstp);
        const float* g = src + row * CDIM + c4 * 4;
        asm volatile("cp.async.cg.shared.global [%0], [%1], 16;" :: "r"(dst), "l"(g));
    }
    asm volatile("cp.async.commit_group;");
}

// Per-warp (warp == capsule n, wid<16): s[n] = scale * (vsrc . W_n), squash -> out.
// If gout != nullptr: write final output and return. Else write out_s and w_s[n][c] = W_n @ out.
__device__ __forceinline__ void boundary(float* sm, const float* vsrc_base, int per_n_stride,
                                         float scale, const float* __restrict__ W,
                                         bool write_w, float* gout, int wid, int lane) {
    const float* vsrc = vsrc_base + wid * per_n_stride;
    const float* Wp = W + wid * DD + lane;       // W[c*512 + n*32 + d]
    float s = 0.f;
#pragma unroll 8
    for (int c = 0; c < CDIM; c++) s += vsrc[c] * Wp[c * (NC * DD)];
    s *= scale;
    float ss = s * s;
#pragma unroll
    for (int o = 16; o > 0; o >>= 1) ss += __shfl_xor_sync(0xffffffffu, ss, o);
    float ov = s * rsqrtf(ss + EPS);
    if (gout) { gout[wid * DD + lane] = ov; return; }
    sm[OFF_OUT + wid * DD + lane] = ov;
    __syncwarp();
    if (write_w) {
#pragma unroll
        for (int k = 0; k < 8; k++) {
            int c = lane + 32 * k;
            const float* Wc = W + c * (NC * DD) + wid * DD;
            float a = 0.f;
#pragma unroll
            for (int dd = 0; dd < DD; dd += 4) {
                float4 w4 = *(const float4*)(Wc + dd);
                a += w4.x * sm[OFF_OUT + wid * DD + dd + 0];
                a += w4.y * sm[OFF_OUT + wid * DD + dd + 1];
                a += w4.z * sm[OFF_OUT + wid * DD + dd + 2];
                a += w4.w * sm[OFF_OUT + wid * DD + dd + 3];
            }
            sm[OFF_W + wid * CDIM + c] = a;
        }
    }
}

__global__ __launch_bounds__(THREADS, 1)
void caps_route_kernel(const float* __restrict__ u_vecs, const float* __restrict__ W,
                       float* __restrict__ gout) {
    extern __shared__ float sm[];
    const int t = threadIdx.x, wid = t >> 5, lane = t & 31;
    const int g = wid >> 4;                // ping-pong group 0/1
    const int gt = t & (GSIZE - 1);        // thread id within group
    const int gwid = gt >> 5;              // warp id within group (0..15)
    const int b = blockIdx.x;
    const float* u = u_vecs + (size_t)b * IC * CDIM;

    float* blogg = &sm[OFF_BLOG + g * 8704];
    float* csg   = &sm[OFF_CS + g * 1024];

    // step-A roles: warp = (kg in 8 -> 32 ch, nh in 2 -> 8 n); lane -> rows lane, lane+32
    const int a_kg = gwid & 7;
    const int a_nh = gwid >> 3;

    // step-C roles: warp = (nh, chq, rgrp); lane = channel-pair within quarter
    const int c_nh   = gwid & 1;            // 8 n at c_nh*8
    const int c_chq  = (gwid >> 1) & 3;     // 64-channel quarter
    const int c_rgrp = gwid >> 3;           // 32-row group (0..1)
    const int c_c2   = c_chq * 32 + lane;   // channel-pair index 0..127
    const int c_q    = c_c2 >> 1;           // float4 quad 0..63
    const int c_sub  = (c_c2 & 1) * 2;      // offset within quad

    // ---------- pass 0: usum[c] = sum_i u[i][c]; out0 = squash(usum/16 @ W_n) ----------
    {
        int c4 = t & 63, rg = t >> 6;     // 16 row groups x 64 quads
        const float* up = u + (size_t)rg * CDIM + c4 * 4;
        float4 a = make_float4(0.f, 0.f, 0.f, 0.f);
#pragma unroll 8
        for (int i = 0; i < IC / 16; i++) {
            float4 v = *(const float4*)(up + (size_t)i * 16 * CDIM);
            a.x += v.x; a.y += v.y; a.z += v.z; a.w += v.w;
        }
        *(float4*)&sm[OFF_BLOG + rg * CDIM + c4 * 4] = a;
    }
    __syncthreads();
    if (t < 256) {
        float a = 0.f;
#pragma unroll
        for (int rg = 0; rg < 16; rg++) a += sm[OFF_BLOG + rg * CDIM + t];
        sm[OFF_USUM + t] = a;
    }
    __syncthreads();
    if (wid < 16) boundary(sm, &sm[OFF_USUM], 0, 1.f / 16.f, W, true, nullptr, wid, lane);
    __syncthreads();

    // ---------- 2 fused routing passes, ping-pong groups; alternate traversal dir ----------
    for (int pass = 0; pass < 2; ++pass) {
        unsigned long long vac2[8];        // 8 capsules x 1 channel-pair
#pragma unroll
        for (int m = 0; m < 8; m++) vac2[m] = 0ull;

        // pass 0 reverse (rides pass-0's L2 tail), pass 1 forward (rides pass-0-routing's tail)
        const bool rev = (pass == 0);
        int c0 = rev ? (NCHUNK - 2 + g) : g;
        prefetch_chunk(sm, u, c0, g, gt);

        for (int k = 0; k < NCHUNK / 2; ++k) {
            int c = rev ? (NCHUNK - 2 + g - 2 * k) : (g + 2 * k);
            asm volatile("cp.async.wait_group 0;" ::: "memory");
            GBAR(g);
            const float* ub = &sm[OFF_U + g * (CH * CDIM)];

            // --- step A: blog partials, 8n x 32ch per warp, 2 rows/lane, acc held ---
            {
                const int r0 = lane, r1 = lane + 32;
                const int s0 = (r0 & 15), s1 = (r1 & 15);
                const float* rb0 = ub + r0 * CDIM;
                const float* rb1 = ub + r1 * CDIM;
                const float* wbase = &sm[OFF_W + a_nh * 8 * CDIM];
                unsigned long long acc[8][2];
#pragma unroll
                for (int m = 0; m < 8; m++) { acc[m][0] = 0ull; acc[m][1] = 0ull; }
#pragma unroll
                for (int j = 0; j < 8; j++) {
                    int cq = a_kg * 8 + j;
                    ulonglong2 uA = *(const ulonglong2*)(rb0 + ((cq ^ s0) << 2));
                    ulonglong2 uB = *(const ulonglong2*)(rb1 + ((cq ^ s1) << 2));
#pragma unroll
                    for (int m = 0; m < 8; m++) {
                        ulonglong2 w2 = *(const ulonglong2*)(wbase + m * CDIM + cq * 4);
                        acc[m][0] = ffma2(uA.x, w2.x, acc[m][0]);
                        acc[m][0] = ffma2(uA.y, w2.y, acc[m][0]);
                        acc[m][1] = ffma2(uB.x, w2.x, acc[m][1]);
                        acc[m][1] = ffma2(uB.y, w2.y, acc[m][1]);
                    }
                }
                float* bb = blogg + a_kg * (64 * 17) + a_nh * 8;
#pragma unroll
                for (int m = 0; m < 8; m++) {
                    float2 f0 = upk(acc[m][0]), f1 = upk(acc[m][1]);
                    bb[r0 * 17 + m] = f0.x + f0.y;
                    bb[r1 * 17 + m] = f1.x + f1.y;
                }
            }
            GBAR(g);

            // --- softmax over n: (row, n) per thread, 2 rows; gather 8 kg-partials ---
            {
                const int n = gt & 15, ii0 = gt >> 4;
#pragma unroll
                for (int s2 = 0; s2 < 2; s2++) {
                    int ii = ii0 + s2 * 32;
                    float bl = 0.f;
#pragma unroll
                    for (int kg = 0; kg < 8; kg++)
                        bl += blogg[kg * (64 * 17) + ii * 17 + n];
                    float m = bl;
#pragma unroll
                    for (int o = 8; o > 0; o >>= 1) m = fmaxf(m, __shfl_xor_sync(0xffffffffu, m, o, 16));
                    float e = __expf(bl - m);
                    float ssum = e;
#pragma unroll
                    for (int o = 8; o > 0; o >>= 1) ssum += __shfl_xor_sync(0xffffffffu, ssum, o, 16);
                    csg[ii * NC + n] = e / ssum;   // [row][n]
                }
            }
            GBAR(g);

            // --- step C: v[n][chpair] += c[n][row] * u[row][chpair]; 8n x 2ch, 32 rows ---
            {
                const float* csb = csg + c_nh * 8;
#pragma unroll 4
                for (int r32 = 0; r32 < 32; r32++) {
                    int row = c_rgrp * 32 + r32;
                    unsigned long long uu =
                        *(const unsigned long long*)(ub + row * CDIM + ((c_q ^ (row & 15)) << 2) + c_sub);
                    float4 ca = *(const float4*)(csb + row * NC);
                    float4 cb = *(const float4*)(csb + row * NC + 4);
                    vac2[0] = ffma2(uu, pk2(ca.x), vac2[0]);
                    vac2[1] = ffma2(uu, pk2(ca.y), vac2[1]);
                    vac2[2] = ffma2(uu, pk2(ca.z), vac2[2]);
                    vac2[3] = ffma2(uu, pk2(ca.w), vac2[3]);
                    vac2[4] = ffma2(uu, pk2(cb.x), vac2[4]);
                    vac2[5] = ffma2(uu, pk2(cb.y), vac2[5]);
                    vac2[6] = ffma2(uu, pk2(cb.z), vac2[6]);
                    vac2[7] = ffma2(uu, pk2(cb.w), vac2[7]);
                }
            }
            GBAR(g);   // group done reading its buffer; safe to refill

            if (k + 1 < NCHUNK / 2) {
                int cn = rev ? (c - 2) : (c + 2);
                prefetch_chunk(sm, u, cn, g, gt);
            }
        }
        __syncthreads();   // both groups done; U dead; VPART (alias) live

        // dump register v partials (copies: g*2 + rgrp), reduce 4 copies
        {
#pragma unroll
            for (int m = 0; m < 8; m++) {
                int n = c_nh * 8 + m;
                *(unsigned long long*)&sm[OFF_VPART + (g * 2 + c_rgrp) * (NC * CDIM)
                                          + n * CDIM + c_c2 * 2] = vac2[m];
            }
        }
        __syncthreads();
        {
            int q = t;    // NC*CDIM/4 = 1024 quads == THREADS
            float4 a = *(float4*)&sm[OFF_VPART + 4 * q];
            float4 b1 = *(float4*)&sm[OFF_VPART + 1 * NC * CDIM + 4 * q];
            float4 b2 = *(float4*)&sm[OFF_VPART + 2 * NC * CDIM + 4 * q];
            float4 b3 = *(float4*)&sm[OFF_VPART + 3 * NC * CDIM + 4 * q];
            a.x += b1.x + b2.x + b3.x;
            a.y += b1.y + b2.y + b3.y;
            a.z += b1.z + b2.z + b3.z;
            a.w += b1.w + b2.w + b3.w;
            *(float4*)&sm[OFF_VPART + 4 * q] = a;
        }
        __syncthreads();

        bool last = (pass == 1);
        if (wid < 16)
            boundary(sm, &sm[OFF_VPART], CDIM, 1.f, W, !last,
                     last ? (gout + (size_t)b * NC * DD) : nullptr, wid, lane);
        __syncthreads();   // protects next pass's prefetch into aliased U region
    }
}

extern "C" void kernel_launch(void* const* d_in, const int* in_sizes, int n_in,
                              void* d_out, int out_size) {
    const float* u_vecs = (const float*)d_in[0];   // (128, 1024, 256) fp32
    const float* W      = (const float*)d_in[1];   // (256, 512) fp32
    float* out          = (float*)d_out;           // (128, 16, 32) fp32

    cudaFuncSetAttribute(caps_route_kernel, cudaFuncAttributeMaxDynamicSharedMemorySize, SMEM_BYTES);
    caps_route_kernel<<<128, THREADS, SMEM_BYTES>>>(u_vecs, W, out);
}